// round 2
// baseline (speedup 1.0000x reference)
#include <cuda_runtime.h>
#include <cuda_bf16.h>

// WaveletTransformLayer: x (B=128, T=2048, F=32) fp32
// out per (b,f): [detail1 (2047) | detail2 (2044) | detail3 (2037) | approx3 (2037)] / T
// All four outputs at position t are FIR filters over taps s[t .. t+11]:
//   d1[t] = (s1-s0)/2/T
//   d2[t] = (-s0 -2s1 -2s2 +2s3 +3s4)/8/T
//   ma3[t] = (s0+3s1+5s2+7s3+8(s4+s5+s6+s7)+7s8+5s9+3s10+s11)/64/T
//   d3[t] = ma2[t+7] - ma3[t],  ma2[t+7] = (s7+2(s8+s9+s10)+s11)/8/T
//   a3[t] = ma3[t]
//
// R2 design: 4 positions per thread; 5x LDS.128 taps; 4x STG.128 stores.
// Out-address alignment: elem index mod 4 = (f + off + tg) mod 4  (8165 == 1 mod 4).
// Per f, shift alpha = (-f) & 3 aligns d1/a3; (alpha+1) & 3 aligns d2/d3.
// Compile-time specialization on f&3 keeps all tap indices constant.

#define T_FULL 2048
#define F_DIM  32
#define TILE   256
#define SCOLS  276          // TILE + 20 halo; multiple of 4 -> 16B-aligned smem rows
#define NOUT   8165
#define OFF_D2 2047
#define OFF_D3 4091
#define OFF_A3 6128
#define LEN_D1 2047
#define LEN_D2 2044
#define LEN_A3 2037
#define NTHREADS 256

#define C1f (1.0f / 4096.0f)     // 1/(2*T)
#define C2f (1.0f / 16384.0f)    // 1/(8*T)
#define C3f (1.0f / 131072.0f)   // 1/(64*T)

__device__ __forceinline__ float ma3_sum(const float* __restrict__ r) {
    return r[0] + 3.0f*r[1] + 5.0f*r[2] + 7.0f*r[3]
         + 8.0f*(r[4] + r[5] + r[6] + r[7])
         + 7.0f*r[8] + 5.0f*r[9] + 3.0f*r[10] + r[11];
}

__device__ __forceinline__ float ma2_7_sum(const float* __restrict__ r) {
    return r[7] + 2.0f*(r[8] + r[9] + r[10]) + r[11];
}

__device__ __forceinline__ void store4(float* __restrict__ p,
                                       float a, float b, float c, float d, int nv) {
    if (nv >= 4) {
        *reinterpret_cast<float4*>(p) = make_float4(a, b, c, d);   // 16B-aligned by construction
    } else if (nv > 0) {
        p[0] = a;
        if (nv > 1) p[1] = b;
        if (nv > 2) p[2] = c;
    }
}

// A = alignment shift for d1/a3 sections; B = (A+1)&3 for d2/d3 sections.
template<int A>
__device__ __forceinline__ void proc(const float r[20], float* __restrict__ row,
                                     int tgb, bool head) {
    constexpr int B   = (A + 1) & 3;
    constexpr int LO  = (A == 3) ? 0 : A;         // ma3 eval window start
    constexpr int CNT = (A == 3) ? 7 : 5;         // ma3 evals covering both A.. and B.. windows

    float m3[CNT];
    #pragma unroll
    for (int k = 0; k < CNT; k++) m3[k] = ma3_sum(r + LO + k) * C3f;

    // detail1 (shift A)
    {
        const int tg = tgb + A;
        store4(row + tg,
               (r[A+1]-r[A+0])*C1f, (r[A+2]-r[A+1])*C1f,
               (r[A+3]-r[A+2])*C1f, (r[A+4]-r[A+3])*C1f,
               LEN_D1 - tg);
    }
    // detail2 (shift B)
    {
        const int tg = tgb + B;
        float o[4];
        #pragma unroll
        for (int e = 0; e < 4; e++)
            o[e] = (3.0f*r[B+e+4] + 2.0f*r[B+e+3] - 2.0f*r[B+e+2]
                    - 2.0f*r[B+e+1] - r[B+e]) * C2f;
        store4(row + OFF_D2 + tg, o[0], o[1], o[2], o[3], LEN_D2 - tg);
    }
    // detail3 (shift B)
    {
        const int tg = tgb + B;
        float o[4];
        #pragma unroll
        for (int e = 0; e < 4; e++)
            o[e] = ma2_7_sum(r + B + e) * C2f - m3[B + e - LO];
        store4(row + OFF_D3 + tg, o[0], o[1], o[2], o[3], LEN_A3 - tg);
    }
    // approx3 (shift A)
    {
        const int tg = tgb + A;
        store4(row + OFF_A3 + tg,
               m3[A-LO], m3[A+1-LO], m3[A+2-LO], m3[A+3-LO],
               LEN_A3 - tg);
    }
    // Head scalars: global positions [0, A) / [0, B) not covered by aligned chunks.
    if (head) {
        #pragma unroll
        for (int e = 0; e < A; e++) {
            row[e]          = (r[e+1] - r[e]) * C1f;
            row[OFF_A3 + e] = ma3_sum(r + e) * C3f;
        }
        #pragma unroll
        for (int e = 0; e < B; e++) {
            row[OFF_D2 + e] = (3.0f*r[e+4] + 2.0f*r[e+3] - 2.0f*r[e+2]
                               - 2.0f*r[e+1] - r[e]) * C2f;
            row[OFF_D3 + e] = ma2_7_sum(r + e) * C2f - ma3_sum(r + e) * C3f;
        }
    }
}

__global__ __launch_bounds__(NTHREADS)
void wavelet_fir_kernel(const float* __restrict__ x, float* __restrict__ out) {
    __shared__ __align__(16) float s[F_DIM * SCOLS];

    const int t0  = blockIdx.x * TILE;
    const int b   = blockIdx.y;
    const int tid = threadIdx.x;

    const float* __restrict__ xb = x + (size_t)b * (T_FULL * F_DIM);

    // Fill: transpose (t,f) -> smem[f][t]. LDG.128 along f (coalesced),
    // 4 scalar STS (4-way bank conflict tolerated; fill is a small fraction of work).
    for (int idx = tid; idx < (F_DIM * SCOLS) / 4; idx += NTHREADS) {
        const int t  = idx >> 3;
        const int fg = (idx & 7) << 2;
        const int tg = t0 + t;
        float4 v = make_float4(0.0f, 0.0f, 0.0f, 0.0f);
        if (tg < T_FULL) v = *reinterpret_cast<const float4*>(xb + tg * F_DIM + fg);
        s[(fg + 0) * SCOLS + t] = v.x;
        s[(fg + 1) * SCOLS + t] = v.y;
        s[(fg + 2) * SCOLS + t] = v.z;
        s[(fg + 3) * SCOLS + t] = v.w;
    }
    __syncthreads();

    float* __restrict__ ob = out + (size_t)b * (F_DIM * NOUT);

    // Compute: work item = (f, chunk j of 4 positions). Warp-uniform f (64 chunks per f),
    // conflict-free LDS.128 (chunk-stride-1 per lane), fully coalesced STG.128.
    for (int i = tid; i < F_DIM * (TILE / 4); i += NTHREADS) {
        const int f = i >> 6;
        const int j = i & 63;
        const float* __restrict__ sp = s + f * SCOLS + 4 * j;

        float r[20];
        #pragma unroll
        for (int k = 0; k < 5; k++) {
            const float4 v = *reinterpret_cast<const float4*>(sp + 4 * k);
            r[4*k+0] = v.x; r[4*k+1] = v.y; r[4*k+2] = v.z; r[4*k+3] = v.w;
        }

        float* __restrict__ row = ob + f * NOUT;
        const int  tgb  = t0 + 4 * j;
        const bool head = (tgb == 0);

        switch (f & 3) {                      // alpha = (4 - (f&3)) & 3
            case 0:  proc<0>(r, row, tgb, head); break;
            case 1:  proc<3>(r, row, tgb, head); break;
            case 2:  proc<2>(r, row, tgb, head); break;
            default: proc<1>(r, row, tgb, head); break;
        }
    }
}

extern "C" void kernel_launch(void* const* d_in, const int* in_sizes, int n_in,
                              void* d_out, int out_size) {
    const float* x = (const float*)d_in[0];
    float* out = (float*)d_out;
    dim3 grid(T_FULL / TILE, 128);
    wavelet_fir_kernel<<<grid, NTHREADS>>>(x, out);
}